// round 16
// baseline (speedup 1.0000x reference)
#include <cuda_runtime.h>
#include <cuda_bf16.h>
#include <cstdint>

#define BATCH 2048
#define CAND  16
#define DIM   256
#define ADJW  96                    // 2*3*16
#define OUTW  (DIM + ADJW + 1)      // 353
#define THRED 0.8f

// ---- fused kernel geometry ----
#define NB     7                    // batches per block
#define SLOTS  (NB + 6)             // 13 batch tiles incl. +-3 halo
#define BPAD   264                  // bf16 row stride (132 words == 4 mod 32: ldsm clean)
#define FTHR   448                  // threads (14 warps)
#define NROWST (SLOTS * CAND)       // 208 tile rows

#define OFF_TILES  0
#define SZ_TILES   (NROWST * BPAD * 2)                  // 109824 B
#define OFF_RSUM   (OFF_TILES + SZ_TILES)
#define SZ_RSUM    (NB * 6 * CAND * 4)                  // 2688 B
#define OFF_NSQ    (OFF_RSUM + SZ_RSUM)
#define SZ_NSQ     (NROWST * 4)                         // 832 B
#define OFF_NMV    (OFF_NSQ + SZ_NSQ)
#define SZ_NMV     (NROWST * 4)                         // 832 B
#define SMEM_TOTAL (OFF_NMV + SZ_NMV)                   // 114176 B -> 2 CTAs/SM

#define FGRID ((BATCH + NB - 1) / NB)                   // 293 blocks ~ one wave

__device__ __forceinline__ uint32_t smem_u32(const void* p) {
    uint32_t a;
    asm("{ .reg .u64 t; cvta.to.shared.u64 t, %1; cvt.u32.u64 %0, t; }"
        : "=r"(a) : "l"(p));
    return a;
}

__device__ __forceinline__ void ldsm4(uint32_t addr, uint32_t& r0, uint32_t& r1,
                                      uint32_t& r2, uint32_t& r3) {
    asm volatile("ldmatrix.sync.aligned.m8n8.x4.shared.b16 {%0,%1,%2,%3}, [%4];"
                 : "=r"(r0), "=r"(r1), "=r"(r2), "=r"(r3) : "r"(addr));
}

__device__ __forceinline__ void mma16816(float* c, uint32_t a0, uint32_t a1,
                                         uint32_t a2, uint32_t a3,
                                         uint32_t b0, uint32_t b1) {
    asm volatile(
        "mma.sync.aligned.m16n8k16.row.col.f32.bf16.bf16.f32 "
        "{%0,%1,%2,%3}, {%4,%5,%6,%7}, {%8,%9}, {%0,%1,%2,%3};\n"
        : "+f"(c[0]), "+f"(c[1]), "+f"(c[2]), "+f"(c[3])
        : "r"(a0), "r"(a1), "r"(a2), "r"(a3), "r"(b0), "r"(b1));
}

// ---------------------------------------------------------------------------
// K_all: one kernel for both output regions.
//  cols [256,353): band cosine adjacency. Norms computed in the LOAD phase
//    (dot+shfl -> nsq), invn recomputed per-consumer (rsqrt of nsq), row-sum
//    exchange via a per-warp-pair named barrier. One block-wide sync total.
//  cols [0,256):   neighbor-mean, fp32, coalesced, 13 window loads upfront.
// ---------------------------------------------------------------------------
__global__ __launch_bounds__(FTHR, 2) void k_all(const float* __restrict__ emb,
                                                 const int* __restrict__ nm,
                                                 float* __restrict__ out) {
    extern __shared__ __align__(16) char smraw[];
    __nv_bfloat16* tiles = reinterpret_cast<__nv_bfloat16*>(smraw + OFF_TILES); // [208][264]
    float* rsum = reinterpret_cast<float*>(smraw + OFF_RSUM);                   // [NB][6][16]
    float* nsq  = reinterpret_cast<float*>(smraw + OFF_NSQ);                    // [208]
    float* nmv  = reinterpret_cast<float*>(smraw + OFF_NMV);                    // [208]

    const int b0   = blockIdx.x * NB;
    const int t    = threadIdx.x;
    const int wid  = t >> 5;
    const int lane = t & 31;

    // ---- streaming copy+cast + norm accumulate: 208 rows ----
    const int l8 = lane * 8;
    for (int r = wid; r < NROWST; r += FTHR / 32) {
        const int bb = b0 - 3 + (r >> 4);
        float4 v0 = make_float4(0.f, 0.f, 0.f, 0.f);
        float4 v1 = v0;
        if ((unsigned)bb < BATCH) {
            const float4* src = reinterpret_cast<const float4*>(
                emb + ((size_t)bb * CAND + (r & 15)) * DIM);
            v0 = src[lane * 2];
            v1 = src[lane * 2 + 1];
        }
        __nv_bfloat162 o[4];
        o[0] = __floats2bfloat162_rn(v0.x, v0.y);
        o[1] = __floats2bfloat162_rn(v0.z, v0.w);
        o[2] = __floats2bfloat162_rn(v1.x, v1.y);
        o[3] = __floats2bfloat162_rn(v1.z, v1.w);
        *reinterpret_cast<uint4*>(&tiles[(size_t)r * BPAD + l8]) = *reinterpret_cast<uint4*>(o);
        // norm of the bf16-rounded row (matches what the MMA dots use)
        float bx0 = __bfloat162float(o[0].x), bx1 = __bfloat162float(o[0].y);
        float bx2 = __bfloat162float(o[1].x), bx3 = __bfloat162float(o[1].y);
        float bx4 = __bfloat162float(o[2].x), bx5 = __bfloat162float(o[2].y);
        float bx6 = __bfloat162float(o[3].x), bx7 = __bfloat162float(o[3].y);
        float ss = bx0*bx0 + bx1*bx1 + bx2*bx2 + bx3*bx3
                 + bx4*bx4 + bx5*bx5 + bx6*bx6 + bx7*bx7;
        #pragma unroll
        for (int off = 16; off; off >>= 1) ss += __shfl_xor_sync(0xffffffffu, ss, off);
        if (lane == 0) nsq[r] = ss;
    }

    // ---- mask cache: nmv[slot][j] (OOB batches -> 0) ----
    if (t < NROWST) {
        const int bb = b0 - 3 + (t >> 4);
        nmv[t] = ((unsigned)bb < BATCH) ? (float)nm[bb * CAND + (t & 15)] : 0.f;
    }
    __syncthreads();    // the ONLY block-wide barrier

    const int g  = lane >> 2;           // 0..7
    const int tg = lane & 3;            // 0..3
    const int jb = tg * 2;
    const int lmoff = (lane & 15) * BPAD + (lane >> 4) * 8;   // elements
    const uint32_t tiles_base = smem_u32(tiles);

    // ---- pair MMAs: warp wid -> bi = wid/2, cps {0,1,2} or {3,4,5} ----
    const int bi = wid >> 1;            // 0..6
    const int cpb = (wid & 1) * 3;      // 0 (left) or 3 (right)
    const int slot = bi + 3;            // center tile slot

    uint32_t aad = tiles_base + (uint32_t)(slot * CAND * BPAD + lmoff) * 2;
    int bslot[3];
    uint32_t bad[3];
    #pragma unroll
    for (int e = 0; e < 3; e++) {
        bslot[e] = (cpb == 0) ? (slot - 1 - e) : (slot + 1 + e);
        bad[e] = tiles_base + (uint32_t)(bslot[e] * CAND * BPAD + lmoff) * 2;
    }

    float acc[3][8];
    #pragma unroll
    for (int e = 0; e < 3; e++)
        #pragma unroll
        for (int x = 0; x < 8; x++) acc[e][x] = 0.f;

    #pragma unroll
    for (int kt = 0; kt < 16; kt++) {
        // batch all 4 ldsm (MLP=4), then the 12 MMAs
        uint32_t a0, a1, a2, a3;
        uint32_t p0, p1, p2, p3;
        uint32_t q0, q1, q2, q3;
        uint32_t s0, s1, s2, s3;
        ldsm4(aad, a0, a1, a2, a3);
        aad += 32;
        ldsm4(bad[0], p0, p1, p2, p3);
        bad[0] += 32;
        ldsm4(bad[1], q0, q1, q2, q3);
        bad[1] += 32;
        ldsm4(bad[2], s0, s1, s2, s3);
        bad[2] += 32;
        mma16816(acc[0],     a0, a1, a2, a3, p0, p2);
        mma16816(acc[0] + 4, a0, a1, a2, a3, p1, p3);
        mma16816(acc[1],     a0, a1, a2, a3, q0, q2);
        mma16816(acc[1] + 4, a0, a1, a2, a3, q1, q3);
        mma16816(acc[2],     a0, a1, a2, a3, s0, s2);
        mma16816(acc[2] + 4, a0, a1, a2, a3, s1, s3);
    }

    // ---- gates from mask cache ----
    float gj[4][3];
    const int js[4] = {jb, jb + 1, jb + 8, jb + 9};
    #pragma unroll
    for (int jx = 0; jx < 4; jx++) {
        float a, b, c;
        if (cpb == 0) {         // left: masks of batches b-1, b-2, b-3
            a = nmv[(slot - 1) * CAND + js[jx]];
            b = nmv[(slot - 2) * CAND + js[jx]];
            c = nmv[(slot - 3) * CAND + js[jx]];
        } else {                // right: masks of batches b, b+1, b+2
            a = nmv[slot * CAND + js[jx]];
            b = nmv[(slot + 1) * CAND + js[jx]];
            c = nmv[(slot + 2) * CAND + js[jx]];
        }
        gj[jx][0] = a;
        gj[jx][1] = a * b;
        gj[jx][2] = a * b * c;
    }

    // ---- per-consumer inverse norms from nsq (no extra barrier needed) ----
    auto inv_of = [&](int row) -> float {
        return rsqrtf(fmaxf(nsq[row], 1e-12f));
    };
    const float inA0 = inv_of(slot * CAND + g);
    const float inA8 = inv_of(slot * CAND + g + 8);

    // ---- epilogue: cosine scale, threshold, gate, partial row sums ----
    #pragma unroll
    for (int e = 0; e < 3; e++) {
        const int cp = cpb + e;
        const float ib0 = inv_of(bslot[e] * CAND + jb);
        const float ib1 = inv_of(bslot[e] * CAND + jb + 1);
        const float ib8 = inv_of(bslot[e] * CAND + jb + 8);
        const float ib9 = inv_of(bslot[e] * CAND + jb + 9);
        auto thr = [](float v, float ge) {
            v = (v > THRED) ? fminf(v, 1.f) : 0.f;
            return v * ge;
        };
        acc[e][0] = thr(acc[e][0] * inA0 * ib0, gj[0][e]);
        acc[e][1] = thr(acc[e][1] * inA0 * ib1, gj[1][e]);
        acc[e][2] = thr(acc[e][2] * inA8 * ib0, gj[0][e]);
        acc[e][3] = thr(acc[e][3] * inA8 * ib1, gj[1][e]);
        acc[e][4] = thr(acc[e][4] * inA0 * ib8, gj[2][e]);
        acc[e][5] = thr(acc[e][5] * inA0 * ib9, gj[3][e]);
        acc[e][6] = thr(acc[e][6] * inA8 * ib8, gj[2][e]);
        acc[e][7] = thr(acc[e][7] * inA8 * ib9, gj[3][e]);

        float sA = acc[e][0] + acc[e][1] + acc[e][4] + acc[e][5]; // row g
        float sB = acc[e][2] + acc[e][3] + acc[e][6] + acc[e][7]; // row g+8
        sA += __shfl_xor_sync(0xffffffffu, sA, 1);
        sA += __shfl_xor_sync(0xffffffffu, sA, 2);
        sB += __shfl_xor_sync(0xffffffffu, sB, 1);
        sB += __shfl_xor_sync(0xffffffffu, sB, 2);
        if (tg == 0) {
            rsum[(bi * 6 + cp) * CAND + g]     = sA;
            rsum[(bi * 6 + cp) * CAND + g + 8] = sB;
        }
    }

    // ---- pair barrier: warps (2bi, 2bi+1) exchange rsum ----
    asm volatile("bar.sync %0, 64;" :: "r"(bi + 1) : "memory");

    // ---- invs in registers: per row 1 / (L1 sum + ones col) ----
    float sAi = 1.0f, sBi = 1.0f;
    #pragma unroll
    for (int cp = 0; cp < 6; cp++) {
        sAi += rsum[(bi * 6 + cp) * CAND + g];
        sBi += rsum[(bi * 6 + cp) * CAND + g + 8];
    }
    const float ivA = 1.0f / fmaxf(sAi, 1e-12f);
    const float ivB = 1.0f / fmaxf(sBi, 1e-12f);

    // ---- normalized adjacency writes (guard partial last block) ----
    if (b0 + bi < BATCH) {
        #pragma unroll
        for (int e = 0; e < 3; e++) {
            const int cp = cpb + e;
            float* oA = out + (size_t)((b0 + bi) * CAND + g)     * OUTW + DIM + cp * CAND + jb;
            float* oB = out + (size_t)((b0 + bi) * CAND + g + 8) * OUTW + DIM + cp * CAND + jb;
            oA[0] = acc[e][0] * ivA;  oA[1] = acc[e][1] * ivA;
            oA[8] = acc[e][4] * ivA;  oA[9] = acc[e][5] * ivA;
            oB[0] = acc[e][2] * ivB;  oB[1] = acc[e][3] * ivB;
            oB[8] = acc[e][6] * ivB;  oB[9] = acc[e][7] * ivB;
        }
        if (cpb == 0 && tg == 0) {   // ones column, rows g and g+8 of batch bi
            out[(size_t)((b0 + bi) * CAND + g)     * OUTW + DIM + ADJW] = ivA;
            out[(size_t)((b0 + bi) * CAND + g + 8) * OUTW + DIM + ADJW] = ivB;
        }
    }

    // ================= neighbor-mean phase (cols [0,256)) =================
    // COALESCED (c = p>>6 shared per 64-thread group, d4 = p&63 contiguous).
    // ALL 13 window loads issued upfront (MLP=13), outputs by static indexing.
    for (int p = t; p < CAND * (DIM / 4); p += FTHR) {
        const int c  = p >> 6;          // 0..15
        const int d4 = p & 63;          // 0..63

        float4 w4[SLOTS];
        #pragma unroll
        for (int s = 0; s < SLOTS; s++) {
            const int bb = b0 - 3 + s;
            float4 x = make_float4(0.f, 0.f, 0.f, 0.f);
            if ((unsigned)bb < BATCH)
                x = *reinterpret_cast<const float4*>(
                    emb + ((size_t)bb * CAND + c) * DIM + d4 * 4);
            w4[s] = x;
        }
        float mmv[SLOTS];
        #pragma unroll
        for (int s = 0; s < SLOTS; s++) mmv[s] = nmv[s * CAND + c];

        #pragma unroll
        for (int bi2 = 0; bi2 < NB; bi2++) {
            const int b = b0 + bi2;
            if (b >= BATCH) continue;
            const float L1 = mmv[bi2 + 2];
            const float L2 = L1 * mmv[bi2 + 1];
            const float L3 = L2 * mmv[bi2];
            const float R1 = mmv[bi2 + 3];
            const float R2 = R1 * mmv[bi2 + 4];
            const float R3 = R2 * mmv[bi2 + 5];
            const float4 wl1 = w4[bi2 + 2], wl2 = w4[bi2 + 1], wl3 = w4[bi2];
            const float4 wr1 = w4[bi2 + 4], wr2 = w4[bi2 + 5], wr3 = w4[bi2 + 6];
            float4 a4;
            a4.x = (wl1.x*L1 + wl2.x*L2 + wl3.x*L3 + wr1.x*R1 + wr2.x*R2 + wr3.x*R3) * (1.f/6.f);
            a4.y = (wl1.y*L1 + wl2.y*L2 + wl3.y*L3 + wr1.y*R1 + wr2.y*R2 + wr3.y*R3) * (1.f/6.f);
            a4.z = (wl1.z*L1 + wl2.z*L2 + wl3.z*L3 + wr1.z*R1 + wr2.z*R2 + wr3.z*R3) * (1.f/6.f);
            a4.w = (wl1.w*L1 + wl2.w*L2 + wl3.w*L3 + wr1.w*R1 + wr2.w*R2 + wr3.w*R3) * (1.f/6.f);
            float* o = out + (size_t)(b * CAND + c) * OUTW + d4 * 4;
            o[0] = a4.x; o[1] = a4.y; o[2] = a4.z; o[3] = a4.w;
        }
    }
}

// ---------------------------------------------------------------------------
extern "C" void kernel_launch(void* const* d_in, const int* in_sizes, int n_in,
                              void* d_out, int out_size) {
    (void)in_sizes; (void)n_in; (void)out_size;
    const float* emb = (const float*)d_in[0];
    const int*   nm  = (const int*)d_in[1];
    float*       out = (float*)d_out;

    (void)cudaFuncSetAttribute(k_all, cudaFuncAttributeMaxDynamicSharedMemorySize,
                               SMEM_TOTAL);

    k_all<<<FGRID, FTHR, SMEM_TOTAL>>>(emb, nm, out);
}